// round 5
// baseline (speedup 1.0000x reference)
#include <cuda_runtime.h>
#include <cstdint>

#define N_NODES 50000
#define F_DIM   64
#define N_EDGES 800000
#define TILE    512
#define HPW     68     // padded h1 row stride in floats (272B, 16B-aligned, odd/16 banks)

// Scratch (static device globals -- no allocation allowed)
__device__ float g_Pa[N_NODES * F_DIM];   // feat @ W1[:64,:] + b1
__device__ float g_Pb[N_NODES * F_DIM];   // feat @ W1[64:,:]
__device__ float g_C[N_NODES];            // per-node accumulated coefficient
__device__ float g_sum;                   // sum of scores
__device__ unsigned int g_cnt;            // count(score < 0.7)
__device__ int g_idx64;                   // 1 if edge_index is int64, 0 if int32

// ---------------------------------------------------------------------------
// Detect index dtype (int64 little-endian high words are all 0 since idx<50K)
// ---------------------------------------------------------------------------
__global__ void detect_kernel(const int* __restrict__ ei32) {
    if (threadIdx.x == 0 && blockIdx.x == 0) {
        int is64 = 1;
        for (int i = 0; i < 512; i++) {
            if (ei32[2 * i + 1] != 0) { is64 = 0; break; }
        }
        g_idx64 = is64;
    }
}

__global__ void zero_kernel() {
    int i = blockIdx.x * 256 + threadIdx.x;
    if (i < N_NODES) g_C[i] = 0.0f;
    if (i == 0) { g_sum = 0.0f; g_cnt = 0u; }
}

// ---------------------------------------------------------------------------
// Precompute Pa/Pb.  Grid-stride: W1 loaded once per block (296 blocks).
// One warp per node; lane j computes outputs j and j+32.
// ---------------------------------------------------------------------------
__global__ __launch_bounds__(256) void precompute_kernel(
    const float* __restrict__ feat,
    const float* __restrict__ W1,
    const float* __restrict__ b1)
{
    __shared__ float W1s[128 * 64];
    __shared__ float b1s[64];
    __shared__ float fs[8][64];

    int tid = threadIdx.x;
    for (int i = tid; i < 128 * 64; i += 256) W1s[i] = W1[i];
    if (tid < 64) b1s[tid] = b1[tid];
    __syncthreads();

    int warp = tid >> 5, lane = tid & 31;

    for (int node = blockIdx.x * 8 + warp; node < N_NODES; node += gridDim.x * 8) {
        fs[warp][lane]      = feat[node * 64 + lane];
        fs[warp][32 + lane] = feat[node * 64 + 32 + lane];
        __syncwarp();

        float aa = b1s[lane], aa2 = b1s[32 + lane];
        float ab = 0.0f,      ab2 = 0.0f;
#pragma unroll
        for (int k = 0; k < 64; k++) {
            float f = fs[warp][k];
            aa  = fmaf(f, W1s[k * 64 + lane],             aa);
            aa2 = fmaf(f, W1s[k * 64 + 32 + lane],        aa2);
            ab  = fmaf(f, W1s[(64 + k) * 64 + lane],      ab);
            ab2 = fmaf(f, W1s[(64 + k) * 64 + 32 + lane], ab2);
        }
        g_Pa[node * 64 + lane]      = aa;
        g_Pa[node * 64 + 32 + lane] = aa2;
        g_Pb[node * 64 + lane]      = ab;
        g_Pb[node * 64 + 32 + lane] = ab2;
        __syncwarp();   // all lanes done reading fs before next iter overwrites
    }
}

// ---------------------------------------------------------------------------
// Edge kernel, tiled: 512 edges per block.
//   Phase A: coalesced gather (16 lanes per edge row) -> h1 tile in smem
//   Phase B: each thread computes TWO edges with packed fma.rn.f32x2
// ---------------------------------------------------------------------------
struct EdgeSmem {
    unsigned long long w2d[64 * 32];  // W2[k][j] duplicated into both f32 halves
    unsigned long long b2d[32];       // b2 duplicated
    float w3s[32];
    int ss[TILE];
    int tt[TILE];
    float red_v[8];
    unsigned red_c[8];
    float hp[TILE * HPW];             // h1 tile (16B-aligned offset by construction)
};

__global__ __launch_bounds__(256, 1) void edge_kernel(
    const void* __restrict__ ei_raw,
    const float* __restrict__ W2,
    const float* __restrict__ b2,
    const float* __restrict__ W3,
    const float* __restrict__ b3,
    float* __restrict__ scores)
{
    extern __shared__ unsigned char smraw[];
    EdgeSmem* S = (EdgeSmem*)smraw;
    int tid = threadIdx.x;
    long long tb = (long long)blockIdx.x * TILE;

    // ---- fill weights (duplicated packs for f32x2) ----
    for (int i = tid; i < 64 * 32; i += 256) {
        float w = W2[i];
        unsigned long long p;
        asm("mov.b64 %0, {%1, %1};" : "=l"(p) : "f"(w));
        S->w2d[i] = p;
    }
    if (tid < 32) {
        float bb = b2[tid];
        unsigned long long p;
        asm("mov.b64 %0, {%1, %1};" : "=l"(p) : "f"(bb));
        S->b2d[tid] = p;
        S->w3s[tid] = W3[tid];
    }

    // ---- load & clamp edge indices for this tile ----
    int idx64 = g_idx64;
    for (int i = tid; i < TILE; i += 256) {
        long long e = tb + i;
        int s = 0, t = 0;
        if (e < N_EDGES) {
            if (idx64) {
                const long long* ei = (const long long*)ei_raw;
                s = (int)ei[e];
                t = (int)ei[N_EDGES + e];
            } else {
                const int* ei = (const int*)ei_raw;
                s = ei[e];
                t = ei[N_EDGES + e];
            }
            s = min(max(s, 0), N_NODES - 1);
            t = min(max(t, 0), N_NODES - 1);
        }
        S->ss[i] = s;
        S->tt[i] = t;
    }
    __syncthreads();

    // ---- Phase A: coalesced gather + relu(Pa[s]+Pb[t]) into smem ----
    {
        int grp = tid >> 4;       // 0..15
        int l16 = tid & 15;       // 0..15 : float4 position within the 64-float row
#pragma unroll 4
        for (int r = 0; r < 32; r++) {
            int e = (r << 4) + grp;
            int s = S->ss[e];
            int t = S->tt[e];
            float4 a  = ((const float4*)(g_Pa + (size_t)s * 64))[l16];
            float4 b4 = ((const float4*)(g_Pb + (size_t)t * 64))[l16];
            float4 h;
            h.x = fmaxf(a.x + b4.x, 0.0f);
            h.y = fmaxf(a.y + b4.y, 0.0f);
            h.z = fmaxf(a.z + b4.z, 0.0f);
            h.w = fmaxf(a.w + b4.w, 0.0f);
            *((float4*)(S->hp + e * HPW + (l16 << 2))) = h;
        }
    }
    __syncthreads();

    // ---- Phase B: two edges per thread, packed f32x2 math ----
    const float* h0p = S->hp + tid * HPW;            // edge tb+tid
    const float* h1p = S->hp + (tid + 256) * HPW;    // edge tb+tid+256

    unsigned long long acc[32];
#pragma unroll
    for (int j = 0; j < 32; j++) acc[j] = S->b2d[j];

#pragma unroll 2
    for (int k = 0; k < 64; k++) {
        unsigned long long hk;
        asm("mov.b64 %0, {%1, %2};" : "=l"(hk) : "f"(h0p[k]), "f"(h1p[k]));
        const ulonglong2* wr = (const ulonglong2*)(S->w2d + (k << 5));
#pragma unroll
        for (int j2 = 0; j2 < 16; j2++) {
            ulonglong2 w = wr[j2];
            asm("fma.rn.f32x2 %0, %1, %2, %0;" : "+l"(acc[2 * j2])     : "l"(hk), "l"(w.x));
            asm("fma.rn.f32x2 %0, %1, %2, %0;" : "+l"(acc[2 * j2 + 1]) : "l"(hk), "l"(w.y));
        }
    }

    float b3v = __ldg(b3);
    float z0 = b3v, z1 = b3v;
#pragma unroll
    for (int j = 0; j < 32; j++) {
        float lo, hi;
        asm("mov.b64 {%0, %1}, %2;" : "=f"(lo), "=f"(hi) : "l"(acc[j]));
        float w = S->w3s[j];
        z0 = fmaf(fmaxf(lo, 0.0f), w, z0);
        z1 = fmaf(fmaxf(hi, 0.0f), w, z1);
    }

    float sc0 = 1.0f / (1.0f + expf(-z0));
    float sc1 = 1.0f / (1.0f + expf(-z1));

    long long e0 = tb + tid;
    long long e1 = e0 + 256;
    bool v0 = (e0 < N_EDGES);
    bool v1 = (e1 < N_EDGES);

    if (v0) {
        scores[e0] = sc0;
        if (sc0 < 0.7f) {
            float c = 0.05f * (1.0f - sc0);
            atomicAdd(&g_C[S->ss[tid]], c);
            atomicAdd(&g_C[S->tt[tid]], c);
        }
    }
    if (v1) {
        scores[e1] = sc1;
        if (sc1 < 0.7f) {
            float c = 0.05f * (1.0f - sc1);
            atomicAdd(&g_C[S->ss[tid + 256]], c);
            atomicAdd(&g_C[S->tt[tid + 256]], c);
        }
    }

    // block reduction of score sum + violation count
    float v = (v0 ? sc0 : 0.0f) + (v1 ? sc1 : 0.0f);
    unsigned c = (unsigned)(v0 && sc0 < 0.7f) + (unsigned)(v1 && sc1 < 0.7f);
#pragma unroll
    for (int o = 16; o > 0; o >>= 1) {
        v += __shfl_down_sync(0xFFFFFFFFu, v, o);
        c += __shfl_down_sync(0xFFFFFFFFu, c, o);
    }
    if ((tid & 31) == 0) { S->red_v[tid >> 5] = v; S->red_c[tid >> 5] = c; }
    __syncthreads();
    if (tid < 8) {
        v = S->red_v[tid];
        c = S->red_c[tid];
#pragma unroll
        for (int o = 4; o > 0; o >>= 1) {
            v += __shfl_down_sync(0xFFu, v, o);
            c += __shfl_down_sync(0xFFu, c, o);
        }
        if (tid == 0) {
            atomicAdd(&g_sum, v);
            atomicAdd(&g_cnt, c);
        }
    }
}

// ---------------------------------------------------------------------------
// Finalize: updated[n][f] = feat[n][f] + C[n] * tanh(feat[n][f])
// ---------------------------------------------------------------------------
__global__ __launch_bounds__(256) void finalize_kernel(
    const float* __restrict__ feat,
    float* __restrict__ out)
{
    int i = blockIdx.x * 256 + threadIdx.x;
    if (i < N_NODES * F_DIM) {
        float f = feat[i];
        float c = g_C[i >> 6];
        out[i] = fmaf(c, tanhf(f), f);
    }
    if (i == 0) {
        out[(size_t)N_NODES * F_DIM + N_EDGES]     = g_sum * (1.0f / (float)N_EDGES);
        out[(size_t)N_NODES * F_DIM + N_EDGES + 1] = (float)g_cnt;
    }
}

// ---------------------------------------------------------------------------
extern "C" void kernel_launch(void* const* d_in, const int* in_sizes, int n_in,
                              void* d_out, int out_size)
{
    const float* feat = (const float*)d_in[0];
    const void*  ei   = d_in[1];
    // d_in[2] = node_positions (unused), d_in[3] = node_radii (unused)
    const float* W1 = (const float*)d_in[4];
    const float* b1 = (const float*)d_in[5];
    const float* W2 = (const float*)d_in[6];
    const float* b2 = (const float*)d_in[7];
    const float* W3 = (const float*)d_in[8];
    const float* b3 = (const float*)d_in[9];

    float* out    = (float*)d_out;
    float* scores = out + (size_t)N_NODES * F_DIM;

    cudaFuncSetAttribute(edge_kernel,
                         cudaFuncAttributeMaxDynamicSharedMemorySize,
                         (int)sizeof(EdgeSmem));

    detect_kernel<<<1, 32>>>((const int*)ei);
    zero_kernel<<<(N_NODES + 255) / 256, 256>>>();
    precompute_kernel<<<296, 256>>>(feat, W1, b1);
    edge_kernel<<<(N_EDGES + TILE - 1) / TILE, 256, sizeof(EdgeSmem)>>>(
        ei, W2, b2, W3, b3, scores);
    finalize_kernel<<<(N_NODES * F_DIM + 255) / 256, 256>>>(feat, out);
}

// round 6
// speedup vs baseline: 1.3203x; 1.3203x over previous
#include <cuda_runtime.h>
#include <cstdint>

#define N_NODES 50000
#define F_DIM   64
#define N_EDGES 800000
#define TILE    256
#define HPW     65     // odd stride: conflict-free per-edge scalar LDS in hot loop

// Scratch (static device globals -- no allocation allowed)
__device__ float g_Pa[N_NODES * F_DIM];   // feat @ W1[:64,:] + b1
__device__ float g_Pb[N_NODES * F_DIM];   // feat @ W1[64:,:]
__device__ float g_C[N_NODES];            // per-node accumulated coefficient
__device__ float g_sum;                   // sum of scores
__device__ unsigned int g_cnt;            // count(score < 0.7)
__device__ int g_idx64;                   // 1 if edge_index is int64, 0 if int32

// ---------------------------------------------------------------------------
// Detect index dtype (int64 little-endian high words are all 0 since idx<50K)
// Parallel: 512 threads each check one high word.
// ---------------------------------------------------------------------------
__global__ void detect_kernel(const int* __restrict__ ei32) {
    __shared__ int bad;
    if (threadIdx.x == 0) bad = 0;
    __syncthreads();
    if (ei32[2 * threadIdx.x + 1] != 0) bad = 1;   // benign race, all write 1
    __syncthreads();
    if (threadIdx.x == 0) g_idx64 = bad ? 0 : 1;
}

__global__ void zero_kernel() {
    int i = blockIdx.x * 256 + threadIdx.x;
    if (i < N_NODES) g_C[i] = 0.0f;
    if (i == 0) { g_sum = 0.0f; g_cnt = 0u; }
}

// ---------------------------------------------------------------------------
// Precompute Pa/Pb.  Grid-stride: W1 loaded once per block (296 blocks).
// One warp per node; lane j computes outputs j and j+32.
// ---------------------------------------------------------------------------
__global__ __launch_bounds__(256) void precompute_kernel(
    const float* __restrict__ feat,
    const float* __restrict__ W1,
    const float* __restrict__ b1)
{
    __shared__ float W1s[128 * 64];
    __shared__ float b1s[64];
    __shared__ float fs[8][64];

    int tid = threadIdx.x;
    for (int i = tid; i < 128 * 64; i += 256) W1s[i] = W1[i];
    if (tid < 64) b1s[tid] = b1[tid];
    __syncthreads();

    int warp = tid >> 5, lane = tid & 31;

    for (int node = blockIdx.x * 8 + warp; node < N_NODES; node += gridDim.x * 8) {
        fs[warp][lane]      = feat[node * 64 + lane];
        fs[warp][32 + lane] = feat[node * 64 + 32 + lane];
        __syncwarp();

        float aa = b1s[lane], aa2 = b1s[32 + lane];
        float ab = 0.0f,      ab2 = 0.0f;
#pragma unroll
        for (int k = 0; k < 64; k++) {
            float f = fs[warp][k];
            aa  = fmaf(f, W1s[k * 64 + lane],             aa);
            aa2 = fmaf(f, W1s[k * 64 + 32 + lane],        aa2);
            ab  = fmaf(f, W1s[(64 + k) * 64 + lane],      ab);
            ab2 = fmaf(f, W1s[(64 + k) * 64 + 32 + lane], ab2);
        }
        g_Pa[node * 64 + lane]      = aa;
        g_Pa[node * 64 + 32 + lane] = aa2;
        g_Pb[node * 64 + lane]      = ab;
        g_Pb[node * 64 + 32 + lane] = ab2;
        __syncwarp();   // all lanes done reading fs before next iter overwrites
    }
}

// ---------------------------------------------------------------------------
// Edge kernel, tiled: 256 edges per block (E divides exactly: 3125 blocks).
//   Phase A: coalesced gather (16 lanes per edge row) -> h1 tile in smem
//   Phase B: thread (p, og) computes outputs [16*og,16*og+16) for the
//            edge pair (p, p+128) with packed fma.rn.f32x2.
//   z combined across the two og-halves via smem partials.
// ---------------------------------------------------------------------------
struct EdgeSmem {
    unsigned long long w2d[64 * 32];  // W2[k][j] duplicated into both f32 halves
    unsigned long long b2d[32];       // b2 duplicated
    float w3s[32];
    int ss[TILE];
    int tt[TILE];
    float2 zp[256];                   // per-thread partial (z0, z1)
    float red_v[8];
    unsigned red_c[8];
    float hp[TILE * HPW];             // h1 tile, edge-major, stride 65
};

__global__ __launch_bounds__(256, 2) void edge_kernel(
    const void* __restrict__ ei_raw,
    const float* __restrict__ W2,
    const float* __restrict__ b2,
    const float* __restrict__ W3,
    const float* __restrict__ b3,
    float* __restrict__ scores)
{
    extern __shared__ unsigned char smraw[];
    EdgeSmem* S = (EdgeSmem*)smraw;
    int tid = threadIdx.x;
    int tb = blockIdx.x * TILE;

    // ---- fill weights (duplicated packs for f32x2) ----
    for (int i = tid; i < 64 * 32; i += 256) {
        float w = W2[i];
        unsigned long long pkd;
        asm("mov.b64 %0, {%1, %1};" : "=l"(pkd) : "f"(w));
        S->w2d[i] = pkd;
    }
    if (tid < 32) {
        float bb = b2[tid];
        unsigned long long pkd;
        asm("mov.b64 %0, {%1, %1};" : "=l"(pkd) : "f"(bb));
        S->b2d[tid] = pkd;
        S->w3s[tid] = W3[tid];
    }

    // ---- load & clamp edge indices for this tile ----
    {
        int idx64 = g_idx64;
        int e = tb + tid;
        int s, t;
        if (idx64) {
            const long long* ei = (const long long*)ei_raw;
            s = (int)ei[e];
            t = (int)ei[N_EDGES + e];
        } else {
            const int* ei = (const int*)ei_raw;
            s = ei[e];
            t = ei[N_EDGES + e];
        }
        s = min(max(s, 0), N_NODES - 1);
        t = min(max(t, 0), N_NODES - 1);
        S->ss[tid] = s;
        S->tt[tid] = t;
    }
    __syncthreads();

    // ---- Phase A: coalesced gather + relu(Pa[s]+Pb[t]) into smem ----
    {
        int grp = tid >> 4;       // 0..15
        int l16 = tid & 15;       // float4 position within the 64-float row
#pragma unroll 4
        for (int r = 0; r < 16; r++) {
            int e = (r << 4) + grp;
            int s = S->ss[e];
            int t = S->tt[e];
            float4 a  = ((const float4*)(g_Pa + (size_t)s * 64))[l16];
            float4 b4 = ((const float4*)(g_Pb + (size_t)t * 64))[l16];
            float* d = S->hp + e * HPW + (l16 << 2);
            d[0] = fmaxf(a.x + b4.x, 0.0f);
            d[1] = fmaxf(a.y + b4.y, 0.0f);
            d[2] = fmaxf(a.z + b4.z, 0.0f);
            d[3] = fmaxf(a.w + b4.w, 0.0f);
        }
    }
    __syncthreads();

    // ---- Phase B: edge pair (p, p+128), output half og ----
    int p  = tid & 127;
    int og = tid >> 7;            // 0 or 1
    const float* hA = S->hp + p * HPW;          // edge tb+p
    const float* hB = S->hp + (p + 128) * HPW;  // edge tb+p+128

    unsigned long long acc[16];
#pragma unroll
    for (int j = 0; j < 16; j++) acc[j] = S->b2d[(og << 4) + j];

#pragma unroll 8
    for (int k = 0; k < 64; k++) {
        unsigned long long hk;
        asm("mov.b64 %0, {%1, %2};" : "=l"(hk) : "f"(hA[k]), "f"(hB[k]));
        const ulonglong2* wr = (const ulonglong2*)(S->w2d + (k << 5) + (og << 4));
#pragma unroll
        for (int j2 = 0; j2 < 8; j2++) {
            ulonglong2 w = wr[j2];
            asm("fma.rn.f32x2 %0, %1, %2, %0;" : "+l"(acc[2 * j2])     : "l"(hk), "l"(w.x));
            asm("fma.rn.f32x2 %0, %1, %2, %0;" : "+l"(acc[2 * j2 + 1]) : "l"(hk), "l"(w.y));
        }
    }

    // partial z over this half's 16 outputs
    float z0 = 0.0f, z1 = 0.0f;
#pragma unroll
    for (int j = 0; j < 16; j++) {
        float lo, hi;
        asm("mov.b64 {%0, %1}, %2;" : "=f"(lo), "=f"(hi) : "l"(acc[j]));
        float w = S->w3s[(og << 4) + j];
        z0 = fmaf(fmaxf(lo, 0.0f), w, z0);
        z1 = fmaf(fmaxf(hi, 0.0f), w, z1);
    }
    S->zp[tid] = make_float2(z0, z1);
    __syncthreads();

    float sc0 = 0.0f, sc1 = 0.0f;
    if (og == 0) {
        float b3v = __ldg(b3);
        float2 o = S->zp[tid + 128];
        float zz0 = z0 + o.x + b3v;
        float zz1 = z1 + o.y + b3v;
        sc0 = 1.0f / (1.0f + expf(-zz0));
        sc1 = 1.0f / (1.0f + expf(-zz1));

        scores[tb + p]       = sc0;
        scores[tb + p + 128] = sc1;

        if (sc0 < 0.7f) {
            float c = 0.05f * (1.0f - sc0);
            atomicAdd(&g_C[S->ss[p]], c);
            atomicAdd(&g_C[S->tt[p]], c);
        }
        if (sc1 < 0.7f) {
            float c = 0.05f * (1.0f - sc1);
            atomicAdd(&g_C[S->ss[p + 128]], c);
            atomicAdd(&g_C[S->tt[p + 128]], c);
        }
    }

    // block reduction of score sum + violation count (og1 threads contribute 0)
    float v = sc0 + sc1;
    unsigned c = (unsigned)(og == 0 && sc0 < 0.7f) + (unsigned)(og == 0 && sc1 < 0.7f);
#pragma unroll
    for (int o = 16; o > 0; o >>= 1) {
        v += __shfl_down_sync(0xFFFFFFFFu, v, o);
        c += __shfl_down_sync(0xFFFFFFFFu, c, o);
    }
    if ((tid & 31) == 0) { S->red_v[tid >> 5] = v; S->red_c[tid >> 5] = c; }
    __syncthreads();
    if (tid < 8) {
        v = S->red_v[tid];
        c = S->red_c[tid];
#pragma unroll
        for (int o = 4; o > 0; o >>= 1) {
            v += __shfl_down_sync(0xFFu, v, o);
            c += __shfl_down_sync(0xFFu, c, o);
        }
        if (tid == 0) {
            atomicAdd(&g_sum, v);
            atomicAdd(&g_cnt, c);
        }
    }
}

// ---------------------------------------------------------------------------
// Finalize: updated[n][f] = feat[n][f] + C[n] * tanh(feat[n][f])
// ---------------------------------------------------------------------------
__global__ __launch_bounds__(256) void finalize_kernel(
    const float* __restrict__ feat,
    float* __restrict__ out)
{
    int i = blockIdx.x * 256 + threadIdx.x;
    if (i < N_NODES * F_DIM) {
        float f = feat[i];
        float c = g_C[i >> 6];
        out[i] = fmaf(c, tanhf(f), f);
    }
    if (i == 0) {
        out[(size_t)N_NODES * F_DIM + N_EDGES]     = g_sum * (1.0f / (float)N_EDGES);
        out[(size_t)N_NODES * F_DIM + N_EDGES + 1] = (float)g_cnt;
    }
}

// ---------------------------------------------------------------------------
extern "C" void kernel_launch(void* const* d_in, const int* in_sizes, int n_in,
                              void* d_out, int out_size)
{
    const float* feat = (const float*)d_in[0];
    const void*  ei   = d_in[1];
    // d_in[2] = node_positions (unused), d_in[3] = node_radii (unused)
    const float* W1 = (const float*)d_in[4];
    const float* b1 = (const float*)d_in[5];
    const float* W2 = (const float*)d_in[6];
    const float* b2 = (const float*)d_in[7];
    const float* W3 = (const float*)d_in[8];
    const float* b3 = (const float*)d_in[9];

    float* out    = (float*)d_out;
    float* scores = out + (size_t)N_NODES * F_DIM;

    cudaFuncSetAttribute(edge_kernel,
                         cudaFuncAttributeMaxDynamicSharedMemorySize,
                         (int)sizeof(EdgeSmem));

    detect_kernel<<<1, 512>>>((const int*)ei);
    zero_kernel<<<(N_NODES + 255) / 256, 256>>>();
    precompute_kernel<<<296, 256>>>(feat, W1, b1);
    edge_kernel<<<N_EDGES / TILE, 256, sizeof(EdgeSmem)>>>(
        ei, W2, b2, W3, b3, scores);
    finalize_kernel<<<(N_NODES * F_DIM + 255) / 256, 256>>>(feat, out);
}